// round 2
// baseline (speedup 1.0000x reference)
#include <cuda_runtime.h>
#include <cuda_bf16.h>
#include <cstdint>

#define CUT 512
#define IMG_H 4096
#define IMG_W 4096
#define HW ((size_t)IMG_H * IMG_W)
#define PLANE ((size_t)CUT * CUT)
#define IMG_STRIDE ((size_t)3 * CUT * CUT)

__global__ __launch_bounds__(256)
void dango_cutouts_kernel(const float* __restrict__ img,
                          const int* __restrict__ sizes,
                          const int* __restrict__ offy,
                          const int* __restrict__ offx,
                          float* __restrict__ out) {
    const int ox = blockIdx.x * blockDim.x + threadIdx.x;  // 0..511
    const int oy = blockIdx.y * blockDim.y + threadIdx.y;  // 0..511
    const int z  = blockIdx.z;                             // 0 = overview, 1..12 = inner crops

    int size, ioy, iox;
    if (z == 0) { size = IMG_W < IMG_H ? IMG_W : IMG_H; ioy = 0; iox = 0; }
    else        { size = sizes[z - 1]; ioy = offy[z - 1]; iox = offx[z - 1]; }

    const float s     = (float)size;
    const float offyf = (float)ioy;
    const float offxf = (float)iox;

    // t = (i + 0.5) * s / 512 - 0.5   (division by 512 is an exact pow2 scale)
    float ty = ((float)oy + 0.5f) * s / 512.0f - 0.5f;
    float y  = offyf + ty;
    y = fminf(fmaxf(y, offyf), offyf + s - 1.0f);
    int   y0 = (int)floorf(y);
    int   y1 = min(y0 + 1, ioy + size - 1);
    float wy = y - (float)y0;

    float tx = ((float)ox + 0.5f) * s / 512.0f - 0.5f;
    float x  = offxf + tx;
    x = fminf(fmaxf(x, offxf), offxf + s - 1.0f);
    int   x0 = (int)floorf(x);
    int   x1 = min(x0 + 1, iox + size - 1);
    float wx = x - (float)x0;

    const size_t r0 = (size_t)y0 * IMG_W;
    const size_t r1 = (size_t)y1 * IMG_W;

    float rgb[3];
    #pragma unroll
    for (int c = 0; c < 3; c++) {
        const float* __restrict__ p = img + (size_t)c * HW;
        float v00 = __ldg(p + r0 + x0);
        float v01 = __ldg(p + r0 + x1);
        float v10 = __ldg(p + r1 + x0);
        float v11 = __ldg(p + r1 + x1);
        float top = v00 * (1.0f - wx) + v01 * wx;
        float bot = v10 * (1.0f - wx) + v11 * wx;
        rgb[c] = top * (1.0f - wy) + bot * wy;
    }
    const float gray = 0.2989f * rgb[0] + 0.587f * rgb[1] + 0.114f * rgb[2];

    const size_t pix = (size_t)oy * CUT + ox;

    if (z == 0) {
        // One full-resize sample feeds all 4 overview images.
        // flipped(y, x) = full(y, 511-x)  =>  write our sample to (y, 511-ox) of images 2,3
        const size_t pixf = (size_t)oy * CUT + (CUT - 1 - ox);
        #pragma unroll
        for (int c = 0; c < 3; c++) {
            out[0 * IMG_STRIDE + c * PLANE + pix]  = rgb[c];
            out[1 * IMG_STRIDE + c * PLANE + pix]  = gray;
            out[2 * IMG_STRIDE + c * PLANE + pixf] = rgb[c];
            out[3 * IMG_STRIDE + c * PLANE + pixf] = gray;
        }
    } else {
        const size_t base = (size_t)(3 + z) * IMG_STRIDE;  // output image 4 + (z-1)
        if (z == 1) {
            // inner[0] is grayscaled
            #pragma unroll
            for (int c = 0; c < 3; c++)
                out[base + c * PLANE + pix] = gray;
        } else {
            #pragma unroll
            for (int c = 0; c < 3; c++)
                out[base + c * PLANE + pix] = rgb[c];
        }
    }
}

extern "C" void kernel_launch(void* const* d_in, const int* in_sizes, int n_in,
                              void* d_out, int out_size) {
    const float* img   = (const float*)d_in[0];   // (1,3,4096,4096) fp32
    // d_in[1] = t (unused scalar)
    const int*   sizes = (const int*)d_in[2];     // (12,)
    const int*   offy  = (const int*)d_in[3];     // (12,)
    const int*   offx  = (const int*)d_in[4];     // (12,)
    float* out = (float*)d_out;                   // (16,3,512,512) fp32

    dim3 block(32, 8, 1);
    dim3 grid(CUT / 32, CUT / 8, 13);  // z=0 overview (4 imgs), z=1..12 inner crops
    dango_cutouts_kernel<<<grid, block>>>(img, sizes, offy, offx, out);
}